// round 4
// baseline (speedup 1.0000x reference)
#include <cuda_runtime.h>
#include <cuda_bf16.h>
#include <stdint.h>

#define Nn   8192
#define FIN  512
#define FOUT 128
#define HID  16
#define NF   (Nn*FOUT)

// ---------------- scratch (device globals: allocation-free) ----------------
__device__ __nv_bfloat16 g_hT_hi[FOUT * Nn];   // [128][8192] bf16, 2MB
__device__ __nv_bfloat16 g_hT_lo[FOUT * Nn];   // 2MB
__device__ float g_part[2 * NF];               // K-split partial sums, 8MB
__device__ float g_degp[2 * Nn];               // K-split partial degrees
__device__ float g_qpart[128];                 // per-block qmp partials

// ---------------- PTX helpers (plain sm_103-safe) ----------------
__device__ __forceinline__ uint32_t smem_u32(const void* p) {
    uint32_t a;
    asm("{ .reg .u64 t; cvta.to.shared.u64 t, %1; cvt.u32.u64 %0, t; }" : "=r"(a) : "l"(p));
    return a;
}
#define CP16(dst, src) \
    asm volatile("cp.async.cg.shared.global [%0], [%1], 16;" :: "r"(dst), "l"(src) : "memory")
#define CP_COMMIT() asm volatile("cp.async.commit_group;" ::: "memory")
#define CP_WAIT1()  asm volatile("cp.async.wait_group 1;" ::: "memory")

#define LDSM4(r0, r1, r2, r3, addr) \
    asm volatile("ldmatrix.sync.aligned.m8n8.x4.shared.b16 {%0,%1,%2,%3},[%4];" \
        : "=r"(r0), "=r"(r1), "=r"(r2), "=r"(r3) : "r"(addr))

#define MMA16816(acc, a, b0, b1) \
    asm volatile("mma.sync.aligned.m16n8k16.row.col.f32.bf16.bf16.f32 " \
        "{%0,%1,%2,%3},{%4,%5,%6,%7},{%8,%9},{%0,%1,%2,%3};" \
        : "+f"((acc)[0]), "+f"((acc)[1]), "+f"((acc)[2]), "+f"((acc)[3]) \
        : "r"((a)[0]), "r"((a)[1]), "r"((a)[2]), "r"((a)[3]), "r"(b0), "r"(b1))

__device__ __forceinline__ uint32_t cvt01(int x, int y) {
    return (x ? 0x3F80u : 0u) | (y ? 0x3F800000u : 0u);
}

// ---------------- kernel 1: h = x@W, emit hT_hi/hT_lo, qmp partials --------
// smem: xs[64][36] @0 (9216B); ws[32][132] @9216 (16896B); v1s[16][128] @26112
// (8192B); sml @34304 (256B); h_s[64][133] @34560 (34048B)
#define K1_SMEM 68608

__global__ void __launch_bounds__(256) k1_feat(
    const float* __restrict__ x, const float* __restrict__ W,
    const float* __restrict__ w1, const float* __restrict__ b1,
    const float* __restrict__ w21, const float* __restrict__ b21,
    const float* __restrict__ w22, const float* __restrict__ b22)
{
    extern __shared__ __align__(16) char sm1[];
    float* xs  = (float*)sm1;
    float* ws  = (float*)(sm1 + 9216);
    float* v1s = (float*)(sm1 + 26112);
    float* sml = (float*)(sm1 + 34304);
    float* h_s = (float*)(sm1 + 34560);

    const int t  = threadIdx.x;
    const int m0 = blockIdx.x * 64;

    for (int i = t; i < HID * FOUT; i += 256) {
        int hh = i >> 7, c = i & 127;
        v1s[i] = w1[hh * 256 + c] + w1[hh * 256 + 128 + c];
    }
    if (t < 16) { sml[t] = b1[t]; sml[16 + t] = w21[t]; sml[32 + t] = w22[t]; }
    if (t == 0) { sml[48] = b21[0]; sml[49] = b22[0]; }

    const int r0 = (t >> 4) << 2;
    const int cb = (t & 15) << 1;
    unsigned long long acc[4][4];
    #pragma unroll
    for (int i = 0; i < 4; i++)
        #pragma unroll
        for (int j = 0; j < 4; j++) acc[i][j] = 0ull;

    for (int kc = 0; kc < 16; kc++) {
        const int k0i = kc * 32;
        #pragma unroll
        for (int i = 0; i < 2; i++) {
            int item = t + 256 * i;
            int rr = item >> 3, g = item & 7;
            *(float4*)&xs[rr * 36 + g * 4] =
                *(const float4*)&x[(size_t)(m0 + rr) * FIN + k0i + g * 4];
        }
        #pragma unroll
        for (int i = 0; i < 4; i++) {
            int item = t + 256 * i;
            int kk = item >> 5, cg = (item & 31) << 2;
            *(float4*)&ws[kk * 132 + cg] =
                *(const float4*)&W[(size_t)(k0i + kk) * FOUT + cg];
        }
        __syncthreads();
        #pragma unroll 8
        for (int kk = 0; kk < 32; kk++) {
            unsigned long long aa[4];
            #pragma unroll
            for (int i = 0; i < 4; i++) {
                float a = xs[(r0 + i) * 36 + kk];
                asm("mov.b64 %0, {%1, %1};" : "=l"(aa[i]) : "r"(__float_as_uint(a)));
            }
            #pragma unroll
            for (int j = 0; j < 4; j++) {
                unsigned long long bp = *(const unsigned long long*)&ws[kk * 132 + cb + 32 * j];
                #pragma unroll
                for (int i = 0; i < 4; i++)
                    asm("fma.rn.f32x2 %0, %1, %2, %0;" : "+l"(acc[i][j]) : "l"(aa[i]), "l"(bp));
            }
        }
        __syncthreads();
    }
    #pragma unroll
    for (int i = 0; i < 4; i++)
        #pragma unroll
        for (int j = 0; j < 4; j++) {
            uint32_t lo, hi;
            asm("mov.b64 {%0, %1}, %2;" : "=r"(lo), "=r"(hi) : "l"(acc[i][j]));
            h_s[(r0 + i) * 133 + cb + 32 * j]     = __uint_as_float(lo);
            h_s[(r0 + i) * 133 + cb + 32 * j + 1] = __uint_as_float(hi);
        }
    __syncthreads();

    // transposed bf16 hi/lo emit: hT[n][m0+r]
    #pragma unroll
    for (int ii = 0; ii < 4; ii++) {
        int item = t + 256 * ii;
        int n = item >> 3, g = item & 7;
        uint32_t hp[4], lp[4];
        #pragma unroll
        for (int q2 = 0; q2 < 4; q2++) {
            float v0 = h_s[(g * 8 + 2 * q2) * 133 + n];
            float v1v = h_s[(g * 8 + 2 * q2 + 1) * 133 + n];
            __nv_bfloat16 h0 = __float2bfloat16(v0), h1 = __float2bfloat16(v1v);
            float l0 = v0 - __bfloat162float(h0), l1 = v1v - __bfloat162float(h1);
            __nv_bfloat16 lb0 = __float2bfloat16(l0), lb1 = __float2bfloat16(l1);
            hp[q2] = (uint32_t)__bfloat16_as_ushort(h0) | ((uint32_t)__bfloat16_as_ushort(h1) << 16);
            lp[q2] = (uint32_t)__bfloat16_as_ushort(lb0) | ((uint32_t)__bfloat16_as_ushort(lb1) << 16);
        }
        size_t off = (size_t)n * Nn + m0 + g * 8;
        *(uint4*)((char*)g_hT_hi + off * 2) = make_uint4(hp[0], hp[1], hp[2], hp[3]);
        *(uint4*)((char*)g_hT_lo + off * 2) = make_uint4(lp[0], lp[1], lp[2], lp[3]);
    }

    // qmp partial (deterministic: staged per-warp, summed by thread 0)
    const int w = t >> 5, l = t & 31;
    float contrib = 0.0f;
    for (int rr = w * 8; rr < w * 8 + 8; rr++) {
        float hv0 = h_s[rr * 133 + l];
        float hv1 = h_s[rr * 133 + l + 32];
        float hv2 = h_s[rr * 133 + l + 64];
        float hv3 = h_s[rr * 133 + l + 96];
        float mu = 0.0f, lv = 0.0f;
        #pragma unroll
        for (int hh = 0; hh < 16; hh++) {
            const float* vr = &v1s[hh * 128];
            float s = hv0 * vr[l] + hv1 * vr[l + 32] + hv2 * vr[l + 64] + hv3 * vr[l + 96];
            #pragma unroll
            for (int o = 16; o > 0; o >>= 1) s += __shfl_xor_sync(0xffffffffu, s, o);
            float u = s + sml[hh];
            u = u > 0.0f ? u : 0.0f;
            mu += u * sml[16 + hh];
            lv += u * sml[32 + hh];
        }
        if (l == 0) {
            mu += sml[48]; lv += sml[49];
            float sig = (lv > 20.0f) ? lv : log1pf(expf(lv));
            contrib += 0.5f * mu * mu - logf(sig);
        }
    }
    if (l == 0) sml[56 + w] = contrib;
    __syncthreads();
    if (t == 0) {
        float s = 0.0f;
        #pragma unroll
        for (int i = 0; i < 8; i++) s += sml[56 + i];
        g_qpart[blockIdx.x] = s;
    }
}

// ---------------- kernel 2: masked aggregation via mma.sync (HMMA) ---------
// Grid 128: CTA (mt, s): rows [mt*128, +128), K-half [s*4096, +4096).
// Buffer: A int32 [128][68] (34816B) | Bh bf16 [128][72] (18432B) | Bl (18432B)
#define ABYTES  34816
#define OFF_BH  34816
#define OFF_BL  53248
#define BUFSZ   71680
#define K2_SMEM (2*BUFSZ)
#define NCH2    64

__global__ void __launch_bounds__(256) k2_aggr(const int* __restrict__ adj)
{
    extern __shared__ __align__(128) char sm2[];
    const uint32_t sb = smem_u32(sm2);
    const int t = threadIdx.x;
    const int mt = blockIdx.x >> 1, s = blockIdx.x & 1;
    const int m0 = mt * 128;
    const int kbase = s * 4096;

    const int w = t >> 5, L = t & 31;
    const int wm = w & 3, wn = w >> 2;      // 4x2 warp grid: 32 rows x 64 cols

    // ---- loader lambda-ish (macro via inline) ----
    const int lr = t >> 1, lq = t & 1;
    const char* aSrcBase = (const char*)(adj + (size_t)(m0 + lr) * Nn + kbase + lq * 32);
    const char* hSrcBase = (const char*)(g_hT_hi + (size_t)lr * Nn + kbase + lq * 32);
    const char* lSrcBase = (const char*)(g_hT_lo + (size_t)lr * Nn + kbase + lq * 32);
    const uint32_t aDstBase = sb + lr * 272 + lq * 128;
    const uint32_t hDstBase = sb + OFF_BH + lr * 144 + lq * 64;
    const uint32_t lDstBase = sb + OFF_BL + lr * 144 + lq * 64;

#define LOAD_CHUNK(c, buf) do {                                                \
    const char* _as = aSrcBase + (size_t)(c) * 256;                            \
    const char* _hs = hSrcBase + (size_t)(c) * 128;                            \
    const char* _ls = lSrcBase + (size_t)(c) * 128;                            \
    uint32_t _ad = aDstBase + (buf) * BUFSZ;                                   \
    uint32_t _hd = hDstBase + (buf) * BUFSZ;                                   \
    uint32_t _ld = lDstBase + (buf) * BUFSZ;                                   \
    CP16(_ad,      _as);       CP16(_ad + 16,  _as + 16);                      \
    CP16(_ad + 32, _as + 32);  CP16(_ad + 48,  _as + 48);                      \
    CP16(_ad + 64, _as + 64);  CP16(_ad + 80,  _as + 80);                      \
    CP16(_ad + 96, _as + 96);  CP16(_ad + 112, _as + 112);                     \
    CP16(_hd,      _hs);       CP16(_hd + 16,  _hs + 16);                      \
    CP16(_hd + 32, _hs + 32);  CP16(_hd + 48,  _hs + 48);                      \
    CP16(_ld,      _ls);       CP16(_ld + 16,  _ls + 16);                      \
    CP16(_ld + 32, _ls + 32);  CP16(_ld + 48,  _ls + 48);                      \
} while (0)

    float acc[2][8][4];
    #pragma unroll
    for (int i = 0; i < 2; i++)
        #pragma unroll
        for (int j = 0; j < 8; j++)
            #pragma unroll
            for (int q = 0; q < 4; q++) acc[i][j][q] = 0.0f;
    int da[2][2] = {{0, 0}, {0, 0}};        // degree partials (wn==0 warps)

    LOAD_CHUNK(0, 0); CP_COMMIT();
    LOAD_CHUNK(1, 1); CP_COMMIT();

    // B ldmatrix lane addressing (constant across chunks)
    const int bn_lane = (L & 7) | ((L >> 4) << 3);
    const int bc_lane = ((L >> 3) & 1) << 3;
    const int arow = wm * 32 + (L >> 2);
    const int acol = 2 * (L & 3);

    for (int c = 0; c < NCH2; c++) {
        CP_WAIT1();
        __syncthreads();
        const int buf = c & 1;
        const char* smA = sm2 + buf * BUFSZ;
        const uint32_t bhB = sb + buf * BUFSZ + OFF_BH;
        const uint32_t blB = sb + buf * BUFSZ + OFF_BL;

        #pragma unroll
        for (int kk = 0; kk < 64; kk += 16) {
            uint32_t a[2][4];
            #pragma unroll
            for (int m = 0; m < 2; m++) {
                const int r = arow + m * 16;
                const int cc = kk + acol;
                int2 v;
                v = *(const int2*)(smA + r * 272 + cc * 4);
                a[m][0] = cvt01(v.x, v.y); if (wn == 0) da[m][0] += v.x + v.y;
                v = *(const int2*)(smA + (r + 8) * 272 + cc * 4);
                a[m][1] = cvt01(v.x, v.y); if (wn == 0) da[m][1] += v.x + v.y;
                v = *(const int2*)(smA + r * 272 + (cc + 8) * 4);
                a[m][2] = cvt01(v.x, v.y); if (wn == 0) da[m][0] += v.x + v.y;
                v = *(const int2*)(smA + (r + 8) * 272 + (cc + 8) * 4);
                a[m][3] = cvt01(v.x, v.y); if (wn == 0) da[m][1] += v.x + v.y;
            }
            #pragma unroll
            for (int p = 0; p < 4; p++) {
                const int n = wn * 64 + p * 16 + bn_lane;
                const uint32_t boff = n * 144 + (kk + bc_lane) * 2;
                uint32_t b0, b1, b2, b3;
                LDSM4(b0, b1, b2, b3, bhB + boff);
                MMA16816(acc[0][2 * p],     a[0], b0, b1);
                MMA16816(acc[0][2 * p + 1], a[0], b2, b3);
                MMA16816(acc[1][2 * p],     a[1], b0, b1);
                MMA16816(acc[1][2 * p + 1], a[1], b2, b3);
                LDSM4(b0, b1, b2, b3, blB + boff);
                MMA16816(acc[0][2 * p],     a[0], b0, b1);
                MMA16816(acc[0][2 * p + 1], a[0], b2, b3);
                MMA16816(acc[1][2 * p],     a[1], b0, b1);
                MMA16816(acc[1][2 * p + 1], a[1], b2, b3);
            }
        }
        __syncthreads();
        if (c + 2 < NCH2) LOAD_CHUNK(c + 2, buf);
        CP_COMMIT();
    }

    // ---- epilogue: partial sums ----
    float* slab = g_part + (size_t)s * NF;
    #pragma unroll
    for (int m = 0; m < 2; m++) {
        const int row = m0 + wm * 32 + m * 16 + (L >> 2);
        #pragma unroll
        for (int nt = 0; nt < 8; nt++) {
            const int col = wn * 64 + nt * 8 + 2 * (L & 3);
            *(float2*)&slab[(size_t)row * FOUT + col] =
                make_float2(acc[m][nt][0], acc[m][nt][1]);
            *(float2*)&slab[(size_t)(row + 8) * FOUT + col] =
                make_float2(acc[m][nt][2], acc[m][nt][3]);
        }
    }
    // ---- partial degrees (wn==0 warps only) ----
    if (wn == 0) {
        #pragma unroll
        for (int m = 0; m < 2; m++) {
            int d0 = da[m][0], d1 = da[m][1];
            d0 += __shfl_xor_sync(0xffffffffu, d0, 1);
            d0 += __shfl_xor_sync(0xffffffffu, d0, 2);
            d1 += __shfl_xor_sync(0xffffffffu, d1, 1);
            d1 += __shfl_xor_sync(0xffffffffu, d1, 2);
            if ((L & 3) == 0) {
                const int row = m0 + wm * 32 + m * 16 + (L >> 2);
                g_degp[s * Nn + row]     = (float)d0;
                g_degp[s * Nn + row + 8] = (float)d1;
            }
        }
    }
#undef LOAD_CHUNK
}

// ---------------- kernel 3: combine K-halves, scale, elu, qmp --------------
__global__ void __launch_bounds__(256) k3_final(float* __restrict__ out, int out_size)
{
    const int idx = blockIdx.x * 256 + threadIdx.x;
    if (idx < NF) {
        const int row = idx >> 7;
        float p = g_part[idx] + g_part[NF + idx];
        float d = g_degp[row] + g_degp[Nn + row];
        float v = p / d;
        out[idx] = v > 0.0f ? v : expm1f(v);
    }
    if (blockIdx.x == 0 && threadIdx.x < 32) {
        float q = g_qpart[threadIdx.x] + g_qpart[threadIdx.x + 32] +
                  g_qpart[threadIdx.x + 64] + g_qpart[threadIdx.x + 96];
        #pragma unroll
        for (int o = 16; o > 0; o >>= 1) q += __shfl_xor_sync(0xffffffffu, q, o);
        if (threadIdx.x == 0 && out_size > NF) out[NF] = q;
    }
}

// ---------------- launch ----------------
extern "C" void kernel_launch(void* const* d_in, const int* in_sizes, int n_in,
                              void* d_out, int out_size) {
    const float* x   = (const float*)d_in[0];
    const int*   adj = (const int*)  d_in[1];
    const float* W   = (const float*)d_in[2];
    const float* w1  = (const float*)d_in[3];
    const float* b1  = (const float*)d_in[4];
    const float* w21 = (const float*)d_in[5];
    const float* b21 = (const float*)d_in[6];
    const float* w22 = (const float*)d_in[7];
    const float* b22 = (const float*)d_in[8];
    float* out = (float*)d_out;

    cudaFuncSetAttribute(k1_feat, cudaFuncAttributeMaxDynamicSharedMemorySize, K1_SMEM);
    cudaFuncSetAttribute(k2_aggr, cudaFuncAttributeMaxDynamicSharedMemorySize, K2_SMEM);

    k1_feat<<<Nn / 64, 256, K1_SMEM>>>(x, W, w1, b1, w21, b21, w22, b22);
    k2_aggr<<<128, 256, K2_SMEM>>>(adj);
    k3_final<<<(NF + 255) / 256, 256>>>(out, out_size);
}